// round 15
// baseline (speedup 1.0000x reference)
#include <cuda_runtime.h>
#include <math.h>
#include <stdint.h>

#define NROWS   131072
#define DDIM    64
#define KCODES  512
#define KH      256            // exact/approx split point
#define QSIZE   8388608
#define ENCSIZE 67108864
#define ENC_OFF (QSIZE + 1)
#define PERP_OFF (QSIZE + 1 + ENCSIZE)

#define ROWS_PB 128
#define NT      128
#define CAP     16             // approx-half candidate cap
#define WF_STR  264            // f32 stride (1056B, 16B-mult)

// dynamic smem layout (bytes)  (identical to R12's proven layout)
#define OFF_WF   0                        // f32 WtF[64][264]: transposed w, k<256   67584
#define OFF_WQ   67584                    // u32 Wq[16][264]: int8x4, k in [256,512) 16896
#define OFF_W2   84480                    // f32 w2s[512]                             2048
#define OFF_H    86528                    // int hist[512]                            2048
#define OFF_CND  88576                    // int cnd[128][CAP]                        8192
#define OFF_CVS  96768                    // f32 cvs[128][CAP]                        8192
#define SMEM_BYTES 104960

__device__ int      g_idx[NROWS];
__device__ int      g_counts[KCODES];
__device__ double   g_loss;
__device__ float    g_w2[KCODES];
__device__ unsigned g_wmax_bits;         // max |w| element (positive-float bits)
__device__ unsigned g_wabs_bits;         // max_k sum_i |w[k][i]|
__device__ uint32_t g_wq[16 * KCODES];   // packed int8 codebook, [i4][k]

// Stats (4 blocks x 128): w2[k] sequential non-fused (mimics jnp.sum(w*w,1));
// zero counters; global max|w| and max per-code sum|w| via idempotent atomicMax.
__global__ void stats_kernel(const float* __restrict__ w) {
    __shared__ float ws[128][65];
    __shared__ float redm[128], reda[128];
    int tid = threadIdx.x;
    int kc0 = blockIdx.x * 128;
    for (int idx = tid; idx < 128 * 64; idx += 128) {
        int row = idx >> 6, col = idx & 63;
        ws[row][col] = w[(kc0 + row) * 64 + col];      // coalesced
    }
    __syncthreads();
    int k = kc0 + tid;
    float s = 0.0f, amax = 0.0f, asum = 0.0f;
    #pragma unroll 8
    for (int i = 0; i < DDIM; ++i) {
        float v = ws[tid][i];
        s = __fadd_rn(s, __fmul_rn(v, v));
        amax = fmaxf(amax, fabsf(v));
        asum += fabsf(v);
    }
    g_w2[k] = s;
    g_counts[k] = 0;
    if (blockIdx.x == 0 && tid == 0) g_loss = 0.0;
    redm[tid] = amax;
    reda[tid] = asum;
    __syncthreads();
    for (int st = 64; st; st >>= 1) {
        if (tid < st) {
            redm[tid] = fmaxf(redm[tid], redm[tid + st]);
            reda[tid] = fmaxf(reda[tid], reda[tid + st]);
        }
        __syncthreads();
    }
    if (tid == 0) {
        atomicMax(&g_wmax_bits, __float_as_uint(redm[0]));   // idempotent
        atomicMax(&g_wabs_bits, __float_as_uint(reda[0]));
    }
}

// Pack int8 codebook with the global scale (reads g_wmax_bits; after stats).
__global__ void pack_kernel(const float* __restrict__ w) {
    float sw = 120.0f / fmaxf(__uint_as_float(g_wmax_bits), 1e-20f);
    int t = blockIdx.x * 128 + threadIdx.x;      // 2048 threads
    for (int u = t; u < 16 * KCODES; u += 2048) {
        int i4 = u >> 9, k = u & 511;
        const float* wp = w + k * DDIM + i4 * 4;
        int q0 = __float2int_rn(wp[0] * sw);
        int q1 = __float2int_rn(wp[1] * sw);
        int q2 = __float2int_rn(wp[2] * sw);
        int q3 = __float2int_rn(wp[3] * sw);
        g_wq[u] = (uint32_t)(q0 & 255) | ((uint32_t)(q1 & 255) << 8)
                | ((uint32_t)(q2 & 255) << 16) | ((uint32_t)(q3 & 255) << 24);
    }
}

// FFMA exact scan of codes [0, KH): reference-identical rounding, strict-<.
#define FFMA_SCAN                                                           \
    for (int g = 0; g < KH; g += 8) {                                       \
        float a0 = 0.f, a1 = 0.f, a2 = 0.f, a3 = 0.f;                       \
        float a4 = 0.f, a5 = 0.f, a6 = 0.f, a7 = 0.f;                       \
        _Pragma("unroll")                                                   \
        for (int i = 0; i < DDIM; ++i) {                                    \
            const float4* wp = (const float4*)(WtF + i * WF_STR + g);       \
            float4 lo = wp[0], hi = wp[1];                                  \
            float fv = f[i];                                                \
            a0 = fmaf(fv, lo.x, a0);                                        \
            a1 = fmaf(fv, lo.y, a1);                                        \
            a2 = fmaf(fv, lo.z, a2);                                        \
            a3 = fmaf(fv, lo.w, a3);                                        \
            a4 = fmaf(fv, hi.x, a4);                                        \
            a5 = fmaf(fv, hi.y, a5);                                        \
            a6 = fmaf(fv, hi.z, a6);                                        \
            a7 = fmaf(fv, hi.w, a7);                                        \
        }                                                                   \
        float av[8] = {a0, a1, a2, a3, a4, a5, a6, a7};                     \
        _Pragma("unroll")                                                   \
        for (int j = 0; j < 8; ++j) {                                       \
            float d = fmaf(-2.0f, av[j], __fadd_rn(S, w2s[g + j]));         \
            if (d < dmin) { dmin = d; kb = g + j; }                         \
        }                                                                   \
    }

// DP4A approx scan of codes [KH, 512): exact int accumulation, append
// candidates vs running smin + 2*m1 (superset of the final sound set).
#define DP4A_SCAN                                                           \
    for (int g = 0; g < KH; g += 8) {                                       \
        int acc[8];                                                         \
        _Pragma("unroll")                                                   \
        for (int j = 0; j < 8; ++j) acc[j] = 0;                             \
        _Pragma("unroll")                                                   \
        for (int i4 = 0; i4 < 16; ++i4) {                                   \
            const uint32_t* qp = Wq + i4 * WF_STR + g;                      \
            uint4 qa = *(const uint4*)qp;                                   \
            uint4 qb = *(const uint4*)(qp + 4);                             \
            int fv4 = (int)fq[i4];                                          \
            acc[0] = __dp4a(fv4, (int)qa.x, acc[0]);                        \
            acc[1] = __dp4a(fv4, (int)qa.y, acc[1]);                        \
            acc[2] = __dp4a(fv4, (int)qa.z, acc[2]);                        \
            acc[3] = __dp4a(fv4, (int)qa.w, acc[3]);                        \
            acc[4] = __dp4a(fv4, (int)qb.x, acc[4]);                        \
            acc[5] = __dp4a(fv4, (int)qb.y, acc[5]);                        \
            acc[6] = __dp4a(fv4, (int)qb.z, acc[6]);                        \
            acc[7] = __dp4a(fv4, (int)qb.w, acc[7]);                        \
        }                                                                   \
        _Pragma("unroll")                                                   \
        for (int j = 0; j < 8; ++j) {                                       \
            float dot = (float)acc[j] * inv;                                \
            float s   = fmaf(-2.0f, dot, w2s[KH + g + j]);                  \
            if (s <= smin + 2.0f * m1) {                                    \
                if (cnt < CAP) { mylist[cnt] = KH + g + j; myvals[cnt] = s; }\
                cnt++;                                                      \
            }                                                               \
            smin = fminf(smin, s);                                          \
        }                                                                   \
    }

// Main: per-thread dual-pipe in two phases (order alternates per warp+block
// to drift co-resident warps into opposite phases). Exact FFMA half needs no
// refine; DP4A half refined exactly (reference rounding, first-index ties).
__global__ __launch_bounds__(NT, 2)
void main_kernel(const float* __restrict__ x, const float* __restrict__ w,
                 float* __restrict__ out) {
    extern __shared__ char sm[];
    float*    WtF = (float*)(sm + OFF_WF);
    uint32_t* Wq  = (uint32_t*)(sm + OFF_WQ);
    float*    w2s = (float*)(sm + OFF_W2);
    int*      hist= (int*)(sm + OFF_H);
    int*      cnd = (int*)(sm + OFF_CND);
    float*    cvs = (float*)(sm + OFF_CVS);

    int tid  = threadIdx.x;
    int lane = tid & 31;
    int wid  = tid >> 5;

    int row0 = blockIdx.x * ROWS_PB;
    int b    = row0 >> 12;
    int hw0  = row0 & 4095;
    const size_t xbase = (size_t)b * 262144 + hw0;

    // ---- load own row (coalesced), S sequential NON-fused (matches ref) ----
    float f[DDIM];
    #pragma unroll
    for (int c = 0; c < DDIM; ++c) f[c] = x[xbase + (size_t)c * 4096 + tid];
    float S = 0.0f;
    #pragma unroll
    for (int c = 0; c < DDIM; ++c) S = __fadd_rn(S, __fmul_rn(f[c], f[c]));

    // ---- int8 pack of f + row stats ----
    float rmax = 0.0f, fabs_sum = 0.0f;
    #pragma unroll
    for (int c = 0; c < DDIM; ++c) { rmax = fmaxf(rmax, fabsf(f[c])); fabs_sum += fabsf(f[c]); }
    float sf = 120.0f / fmaxf(rmax, 1e-20f);
    uint32_t fq[16];
    #pragma unroll
    for (int i4 = 0; i4 < 16; ++i4) {
        int q0 = __float2int_rn(f[4 * i4 + 0] * sf);
        int q1 = __float2int_rn(f[4 * i4 + 1] * sf);
        int q2 = __float2int_rn(f[4 * i4 + 2] * sf);
        int q3 = __float2int_rn(f[4 * i4 + 3] * sf);
        fq[i4] = (uint32_t)(q0 & 255) | ((uint32_t)(q1 & 255) << 8)
               | ((uint32_t)(q2 & 255) << 16) | ((uint32_t)(q3 & 255) << 24);
    }

    // ---- stage: WtF[i][k]=w[k][i] (k<256), Wq (k in [256,512)), w2, hist ----
    for (int idx = tid; idx < KH * DDIM; idx += NT) {
        int k = idx >> 6, i = idx & 63;
        WtF[i * WF_STR + k] = w[idx];                  // coalesced read
    }
    for (int idx = tid; idx < 16 * KH; idx += NT) {
        int i4 = idx >> 8, kk = idx & 255;
        Wq[i4 * WF_STR + kk] = g_wq[i4 * KCODES + KH + kk];
    }
    for (int i = tid; i < KCODES; i += NT) { w2s[i] = g_w2[i]; hist[i] = 0; }
    __syncthreads();

    // ---- sound score-error bound for the DP4A half (R12-proven) ----
    float sw  = 120.0f / fmaxf(__uint_as_float(g_wmax_bits), 1e-20f);
    float dw  = 0.5f / sw;
    float df  = 0.5f / sf;
    float errdot = dw * fabs_sum + df * __uint_as_float(g_wabs_bits) + 64.0f * df * dw;
    float m1  = 2.0f * errdot * 1.05f + 5e-5f;
    float inv = 1.0f / (sf * sw);

    float dmin = __int_as_float(0x7f800000);
    int   kb   = 0;
    float smin = __int_as_float(0x7f800000);
    int   cnt  = 0;
    int*   mylist = cnd + tid * CAP;
    float* myvals = cvs + tid * CAP;

    // ---- two-phase dual-pipe scan; phase order alternates for overlap ----
    if ((wid + blockIdx.x) & 1) {
        DP4A_SCAN
        FFMA_SCAN
    } else {
        FFMA_SCAN
        DP4A_SCAN
    }

    // ---- streamed enc zero-fill (hidden under compute) ----
    {
        float* enc = out + ENC_OFF;
        int wrow0 = row0 + wid * 32;
        float4 z = make_float4(0.f, 0.f, 0.f, 0.f);
        for (int rr = 0; rr < 32; ++rr) {
            float* eb = enc + (size_t)(wrow0 + rr) * KCODES;
            float4* v4 = (float4*)(eb + 3);            // 16B aligned
            #pragma unroll
            for (int it = 0; it < 4; ++it) {
                int j = lane + 32 * it;
                if (j < 127) __stcs(&v4[j], z);
            }
            if (lane < 3) __stcs(&eb[lane], 0.f);
            if (lane == 3) __stcs(&eb[511], 0.f);
        }
    }

    // ---- post-filter vs FINAL mins, exact refine of approx candidates ----
    float thr = fminf(dmin + m1, smin + 2.0f * m1);
    if (cnt <= CAP) {
        for (int j = 0; j < cnt; ++j) {
            if (myvals[j] > thr) continue;
            int k = mylist[j];                         // ascending k
            const float4* wr = (const float4*)(w + (size_t)k * DDIM);
            float a = 0.0f;
            #pragma unroll
            for (int q = 0; q < 16; ++q) {             // i-order 0..63 sequential
                float4 t = __ldg(&wr[q]);
                a = fmaf(f[4 * q + 0], t.x, a);
                a = fmaf(f[4 * q + 1], t.y, a);
                a = fmaf(f[4 * q + 2], t.z, a);
                a = fmaf(f[4 * q + 3], t.w, a);
            }
            float dd = fmaf(-2.0f, a, __fadd_rn(S, w2s[k]));
            if (dd < dmin) { dmin = dd; kb = k; }      // strict <: exact half wins ties
        }
    } else {                                           // overflow: scan approx half
        for (int k = KH; k < KCODES; ++k) {
            const float4* wr = (const float4*)(w + (size_t)k * DDIM);
            float a = 0.0f;
            #pragma unroll
            for (int q = 0; q < 16; ++q) {
                float4 t = __ldg(&wr[q]);
                a = fmaf(f[4 * q + 0], t.x, a);
                a = fmaf(f[4 * q + 1], t.y, a);
                a = fmaf(f[4 * q + 2], t.z, a);
                a = fmaf(f[4 * q + 3], t.w, a);
            }
            float dd = fmaf(-2.0f, a, __fadd_rn(S, w2s[k]));
            if (dd < dmin) { dmin = dd; kb = k; }
        }
    }

    g_idx[row0 + tid] = kb;
    atomicAdd(&hist[kb], 1);

    __syncthreads();   // orders the 1-write after this block's zero-fill

    // ---- one-hot 1-write (fused) ----
    out[ENC_OFF + (size_t)(row0 + tid) * KCODES + kb] = 1.0f;

    // ---- quantized output + loss partials (reference rounding) ----
    const float* wbr = w + (size_t)kb * DDIM;
    float* outp = out + xbase;
    float lsum = 0.0f;
    #pragma unroll
    for (int c = 0; c < DDIM; ++c) {
        float q  = wbr[c];
        float dd = __fsub_rn(q, f[c]);
        outp[(size_t)c * 4096 + tid] = __fadd_rn(f[c], dd);
        lsum = fmaf(dd, dd, lsum);
    }
    #pragma unroll
    for (int o = 16; o; o >>= 1) lsum += __shfl_down_sync(0xffffffffu, lsum, o);
    if (lane == 0) atomicAdd(&g_loss, (double)lsum);

    for (int i = tid; i < KCODES; i += NT)
        if (hist[i]) atomicAdd(&g_counts[i], hist[i]);
}

__global__ void final_kernel(float* __restrict__ out) {
    __shared__ double red[KCODES];
    int t = threadIdx.x;
    float p = (float)g_counts[t] * (1.0f / 131072.0f);
    float term = __fmul_rn(p, logf(__fadd_rn(p, 1e-10f)));
    red[t] = (double)term;
    __syncthreads();
    for (int s = 256; s; s >>= 1) {
        if (t < s) red[t] += red[t + s];
        __syncthreads();
    }
    if (t == 0) {
        out[PERP_OFF] = expf(-(float)red[0]);
        float m = (float)(g_loss / (double)QSIZE);
        out[QSIZE] = __fadd_rn(m, __fmul_rn(0.25f, m));
    }
}

extern "C" void kernel_launch(void* const* d_in, const int* in_sizes, int n_in,
                              void* d_out, int out_size) {
    const float* x = (const float*)d_in[0];
    const float* w = (const float*)d_in[1];
    float* out = (float*)d_out;

    cudaFuncSetAttribute(main_kernel, cudaFuncAttributeMaxDynamicSharedMemorySize,
                         SMEM_BYTES);

    stats_kernel<<<4, 128>>>(w);
    pack_kernel<<<16, 128>>>(w);
    main_kernel<<<NROWS / ROWS_PB, NT, SMEM_BYTES>>>(x, w, out);
    final_kernel<<<1, KCODES>>>(out);
}

// round 16
// speedup vs baseline: 2.4337x; 2.4337x over previous
#include <cuda_runtime.h>
#include <math.h>
#include <stdint.h>

#define NROWS   131072
#define DDIM    64
#define KCODES  512
#define QSIZE   8388608
#define ENCSIZE 67108864
#define ENC_OFF (QSIZE + 1)
#define PERP_OFF (QSIZE + 1 + ENCSIZE)

#define ROWS_PB 128
#define NT      128
#define NBLK    (NROWS / ROWS_PB)
#define CAP     32            // per-row candidate cap
#define WQ_STR  516           // u32 stride of Wq rows in smem

// dynamic smem layout (bytes) -- main kernel (R13-identical + final scratch)
#define OFF_WQ   0                        // u32 Wq[16][516]: int8x4 over i-groups  33024
#define OFF_W2   33024                    // f32 w2s[512]                            2048
#define OFF_H    35072                    // int hist[512]                           2048
#define OFF_CND  37120                    // int cnd[128][CAP]                      16384
#define OFF_CVS  53504                    // f32 cvs[128][CAP]                      16384
#define SMEM_BYTES 69888
// final-reduction scratch reuses OFF_CND region (free by then): 512 doubles

__device__ int      g_idx[NROWS];
__device__ int      g_counts[KCODES];
__device__ double   g_loss;
__device__ float    g_w2[KCODES];
__device__ float    g_wmax;              // max |w| element
__device__ float    g_wabs;              // max_k sum_i |w[k][i]|
__device__ uint32_t g_wq[16 * KCODES];   // packed int8 codebook, [i4][k]
__device__ unsigned g_done;              // completion ticket (reset each run)

// Prep (1 block x 512, 133KB smem): w2[k] sequential non-fused (mimics
// jnp.sum(w*w,1)); zero counters; wmax / wabs via smem reduction; int8 pack.
__global__ void prep_kernel(const float* __restrict__ w) {
    extern __shared__ float ps[];              // ws[512][65] + red[1024]
    float* ws   = ps;                          // stride 65
    float* redm = ps + 512 * 65;
    float* reda = redm + 512;

    int tid = threadIdx.x;
    for (int idx = tid; idx < KCODES * DDIM; idx += 512) {
        int row = idx >> 6, col = idx & 63;
        ws[row * 65 + col] = w[idx];           // coalesced
    }
    g_counts[tid] = 0;
    if (tid == 0) { g_loss = 0.0; g_done = 0; }
    __syncthreads();

    int k = tid;
    const float* wr = ws + k * 65;
    float s = 0.0f, amax = 0.0f, asum = 0.0f;
    #pragma unroll 8
    for (int i = 0; i < DDIM; ++i) {
        float v = wr[i];
        s = __fadd_rn(s, __fmul_rn(v, v));
        amax = fmaxf(amax, fabsf(v));
        asum += fabsf(v);
    }
    g_w2[k] = s;
    redm[tid] = amax;
    reda[tid] = asum;
    __syncthreads();
    for (int st = 256; st; st >>= 1) {
        if (tid < st) {
            redm[tid] = fmaxf(redm[tid], redm[tid + st]);
            reda[tid] = fmaxf(reda[tid], reda[tid + st]);
        }
        __syncthreads();
    }
    float wmax = redm[0];
    if (tid == 0) { g_wmax = wmax; g_wabs = reda[0]; }

    // pack this code's 64 int8 values (global scale from the reduction)
    float sw = 120.0f / fmaxf(wmax, 1e-20f);
    #pragma unroll
    for (int i4 = 0; i4 < 16; ++i4) {
        int q0 = __float2int_rn(wr[4 * i4 + 0] * sw);
        int q1 = __float2int_rn(wr[4 * i4 + 1] * sw);
        int q2 = __float2int_rn(wr[4 * i4 + 2] * sw);
        int q3 = __float2int_rn(wr[4 * i4 + 3] * sw);
        g_wq[i4 * KCODES + k] = (uint32_t)(q0 & 255) | ((uint32_t)(q1 & 255) << 8)
                              | ((uint32_t)(q2 & 255) << 16) | ((uint32_t)(q3 & 255) << 24);
    }
}

// Main (R13-identical scan/refine/outputs) + last-block final reduction.
__global__ __launch_bounds__(NT, 2)
void main_kernel(const float* __restrict__ x, const float* __restrict__ w,
                 float* __restrict__ out) {
    extern __shared__ char sm[];
    uint32_t* Wq  = (uint32_t*)(sm + OFF_WQ);
    float*    w2s = (float*)(sm + OFF_W2);
    int*      hist= (int*)(sm + OFF_H);
    int*      cnd = (int*)(sm + OFF_CND);
    float*    cvs = (float*)(sm + OFF_CVS);

    int tid  = threadIdx.x;
    int lane = tid & 31;
    int wid  = tid >> 5;

    int row0 = blockIdx.x * ROWS_PB;
    int b    = row0 >> 12;
    int hw0  = row0 & 4095;
    const size_t xbase = (size_t)b * 262144 + hw0;

    // ---- load own row (coalesced across lanes) ----
    float f[DDIM];
    #pragma unroll
    for (int c = 0; c < DDIM; ++c) f[c] = x[xbase + (size_t)c * 4096 + tid];

    // ---- S: sequential NON-fused (matches reference) ----
    float S = 0.0f;
    #pragma unroll
    for (int c = 0; c < DDIM; ++c) S = __fadd_rn(S, __fmul_rn(f[c], f[c]));

    // ---- row stats + int8 pack of f ----
    float rmax = 0.0f, fabs_sum = 0.0f;
    #pragma unroll
    for (int c = 0; c < DDIM; ++c) { rmax = fmaxf(rmax, fabsf(f[c])); fabs_sum += fabsf(f[c]); }
    float sf = 120.0f / fmaxf(rmax, 1e-20f);
    uint32_t fq[16];
    #pragma unroll
    for (int i4 = 0; i4 < 16; ++i4) {
        int q0 = __float2int_rn(f[4 * i4 + 0] * sf);
        int q1 = __float2int_rn(f[4 * i4 + 1] * sf);
        int q2 = __float2int_rn(f[4 * i4 + 2] * sf);
        int q3 = __float2int_rn(f[4 * i4 + 3] * sf);
        fq[i4] = (uint32_t)(q0 & 255) | ((uint32_t)(q1 & 255) << 8)
               | ((uint32_t)(q2 & 255) << 16) | ((uint32_t)(q3 & 255) << 24);
    }

    // ---- stage packed codebook + w2 into smem ----
    for (int idx = tid; idx < 16 * KCODES; idx += NT) {
        int i4 = idx >> 9, k = idx & 511;
        Wq[i4 * WQ_STR + k] = g_wq[idx];
    }
    for (int i = tid; i < KCODES; i += NT) { w2s[i] = g_w2[i]; hist[i] = 0; }
    __syncthreads();

    // ---- sound margin (input-quantization error only; int accum is exact) ----
    float sw  = 120.0f / fmaxf(g_wmax, 1e-20f);
    float dw  = 0.5f / sw;
    float df  = 0.5f / sf;
    float errdot = dw * fabs_sum + df * g_wabs + 64.0f * df * dw;
    float margin = 2.0f * errdot * 1.05f + 1e-5f;
    float inv = 1.0f / (sf * sw);

    float runmin = __int_as_float(0x7f800000);
    int   cnt = 0;
    int*   mylist = cnd + tid * CAP;
    float* myvals = cvs + tid * CAP;

    // ---- scan: 8 codes per group, 16 packed i-steps, broadcast LDS ----
    for (int g = 0; g < KCODES; g += 8) {
        int acc[8];
        #pragma unroll
        for (int j = 0; j < 8; ++j) acc[j] = 0;
        #pragma unroll
        for (int i4 = 0; i4 < 16; ++i4) {
            const uint32_t* wp = Wq + i4 * WQ_STR + g;
            uint4 wa = *(const uint4*)wp;
            uint4 wb = *(const uint4*)(wp + 4);
            acc[0] = __dp4a((int)fq[i4], (int)wa.x, acc[0]);
            acc[1] = __dp4a((int)fq[i4], (int)wa.y, acc[1]);
            acc[2] = __dp4a((int)fq[i4], (int)wa.z, acc[2]);
            acc[3] = __dp4a((int)fq[i4], (int)wa.w, acc[3]);
            acc[4] = __dp4a((int)fq[i4], (int)wb.x, acc[4]);
            acc[5] = __dp4a((int)fq[i4], (int)wb.y, acc[5]);
            acc[6] = __dp4a((int)fq[i4], (int)wb.z, acc[6]);
            acc[7] = __dp4a((int)fq[i4], (int)wb.w, acc[7]);
        }
        #pragma unroll
        for (int j = 0; j < 8; ++j) {
            float dot = (float)acc[j] * inv;
            float s   = fmaf(-2.0f, dot, w2s[g + j]);
            if (s <= runmin + margin) {
                if (cnt < CAP) { mylist[cnt] = g + j; myvals[cnt] = s; }
                cnt++;
            }
            runmin = fminf(runmin, s);
        }
    }

    // ---- streamed enc zero-fill (hidden under compute) ----
    {
        float* enc = out + ENC_OFF;
        int wrow0 = row0 + wid * 32;
        float4 z = make_float4(0.f, 0.f, 0.f, 0.f);
        for (int rr = 0; rr < 32; ++rr) {
            float* eb = enc + (size_t)(wrow0 + rr) * KCODES;
            float4* v4 = (float4*)(eb + 3);          // 16B aligned
            #pragma unroll
            for (int it = 0; it < 4; ++it) {
                int j = lane + 32 * it;
                if (j < 127) __stcs(&v4[j], z);
            }
            if (lane < 3) __stcs(&eb[lane], 0.f);
            if (lane == 3) __stcs(&eb[511], 0.f);
        }
    }

    // ---- post-filter vs FINAL min, then exact refinement
    //      (reference-identical rounding, first-index ties) ----
    float thr = runmin + margin;
    float db = __int_as_float(0x7f800000);
    int   kb = 0;
    if (cnt <= CAP) {
        for (int j = 0; j < cnt; ++j) {
            if (myvals[j] > thr) continue;           // drop prefix-min noise
            int k = mylist[j];                       // ascending k order
            const float4* wr = (const float4*)(w + (size_t)k * DDIM);
            float a = 0.0f;
            #pragma unroll
            for (int q = 0; q < 16; ++q) {           // i-order 0..63 sequential
                float4 t = __ldg(&wr[q]);
                a = fmaf(f[4 * q + 0], t.x, a);
                a = fmaf(f[4 * q + 1], t.y, a);
                a = fmaf(f[4 * q + 2], t.z, a);
                a = fmaf(f[4 * q + 3], t.w, a);
            }
            float dd = fmaf(-2.0f, a, __fadd_rn(S, w2s[k]));
            if (dd < db) { db = dd; kb = k; }
        }
    } else {                                         // overflow: full exact scan
        for (int k = 0; k < KCODES; ++k) {
            const float4* wr = (const float4*)(w + (size_t)k * DDIM);
            float a = 0.0f;
            #pragma unroll
            for (int q = 0; q < 16; ++q) {
                float4 t = __ldg(&wr[q]);
                a = fmaf(f[4 * q + 0], t.x, a);
                a = fmaf(f[4 * q + 1], t.y, a);
                a = fmaf(f[4 * q + 2], t.z, a);
                a = fmaf(f[4 * q + 3], t.w, a);
            }
            float dd = fmaf(-2.0f, a, __fadd_rn(S, w2s[k]));
            if (dd < db) { db = dd; kb = k; }
        }
    }

    g_idx[row0 + tid] = kb;
    atomicAdd(&hist[kb], 1);

    __syncthreads();   // orders the 1-write after this block's zero-fill

    // ---- one-hot 1-write (fused) ----
    out[ENC_OFF + (size_t)(row0 + tid) * KCODES + kb] = 1.0f;

    // ---- quantized output + loss partials (reference rounding) ----
    const float* wbr = w + (size_t)kb * DDIM;
    float* outp = out + xbase;
    float lsum = 0.0f;
    #pragma unroll
    for (int c = 0; c < DDIM; ++c) {
        float q  = wbr[c];
        float dd = __fsub_rn(q, f[c]);
        outp[(size_t)c * 4096 + tid] = __fadd_rn(f[c], dd);
        lsum = fmaf(dd, dd, lsum);
    }
    #pragma unroll
    for (int o = 16; o; o >>= 1) lsum += __shfl_down_sync(0xffffffffu, lsum, o);
    if (lane == 0) atomicAdd(&g_loss, (double)lsum);

    for (int i = tid; i < KCODES; i += NT)
        if (hist[i]) atomicAdd(&g_counts[i], hist[i]);

    // ---- completion ticket; last block computes loss + perplexity ----
    __syncthreads();
    __shared__ unsigned s_ticket;
    if (tid == 0) {
        __threadfence();
        s_ticket = atomicAdd(&g_done, 1u);
    }
    __syncthreads();
    if (s_ticket == NBLK - 1) {
        __threadfence();                             // acquire side
        double* red = (double*)(sm + OFF_CND);       // 512 doubles (region free)
        for (int i = tid; i < KCODES; i += NT) {
            int c = atomicAdd(&g_counts[i], 0);      // coherent read
            float p = (float)c * (1.0f / 131072.0f);
            float term = __fmul_rn(p, logf(__fadd_rn(p, 1e-10f)));
            red[i] = (double)term;
        }
        __syncthreads();
        for (int s = 256; s; s >>= 1) {              // same pairing tree as before
            for (int t = tid; t < s; t += NT) red[t] += red[t + s];
            __syncthreads();
        }
        if (tid == 0) {
            out[PERP_OFF] = expf(-(float)red[0]);
            double gl = atomicAdd(&g_loss, 0.0);     // coherent read
            float m = (float)(gl / (double)QSIZE);
            out[QSIZE] = __fadd_rn(m, __fmul_rn(0.25f, m));
            g_done = 0;                              // reset for graph replay
        }
    }
}

extern "C" void kernel_launch(void* const* d_in, const int* in_sizes, int n_in,
                              void* d_out, int out_size) {
    const float* x = (const float*)d_in[0];
    const float* w = (const float*)d_in[1];
    float* out = (float*)d_out;

    cudaFuncSetAttribute(prep_kernel, cudaFuncAttributeMaxDynamicSharedMemorySize,
                         512 * 65 * 4 + 1024 * 4);
    cudaFuncSetAttribute(main_kernel, cudaFuncAttributeMaxDynamicSharedMemorySize,
                         SMEM_BYTES);

    prep_kernel<<<1, 512, 512 * 65 * 4 + 1024 * 4>>>(w);
    main_kernel<<<NBLK, NT, SMEM_BYTES>>>(x, w, out);
}

// round 17
// speedup vs baseline: 3.2848x; 1.3497x over previous
#include <cuda_runtime.h>
#include <math.h>
#include <stdint.h>

#define NROWS   131072
#define DDIM    64
#define KCODES  512
#define QSIZE   8388608
#define ENCSIZE 67108864
#define ENC_OFF (QSIZE + 1)
#define PERP_OFF (QSIZE + 1 + ENCSIZE)

#define ROWS_PB 128
#define NT      128
#define NBLK    (NROWS / ROWS_PB)
#define CAP     32            // per-row candidate cap (thread-local)
#define WQ_STR  516           // u32 stride of Wq rows in smem

// dynamic smem layout (bytes) -- candidates moved to local memory
#define OFF_WQ   0                        // u32 Wq[16][516]                        33024
#define OFF_W2   33024                    // f32 w2s[512]                            2048
#define OFF_H    35072                    // int hist[512]                           2048
#define SMEM_BYTES 37120
// final-reduction scratch reuses OFF_WQ region (free by then): 512 doubles

__device__ int      g_idx[NROWS];
__device__ int      g_counts[KCODES];
__device__ double   g_loss;
__device__ float    g_w2[KCODES];
__device__ float    g_wmax;              // max |w| element
__device__ float    g_wabs;              // max_k sum_i |w[k][i]|
__device__ uint32_t g_wq[16 * KCODES];   // packed int8 codebook, [i4][k]
__device__ unsigned g_done;              // completion ticket (reset each run)

// Prep (1 block x 512): w2[k] sequential non-fused (mimics jnp.sum(w*w,1));
// zero counters; wmax / wabs via smem reduction; int8 pack.
__global__ void prep_kernel(const float* __restrict__ w) {
    extern __shared__ float ps[];              // ws[512][65] + red[1024]
    float* ws   = ps;                          // stride 65
    float* redm = ps + 512 * 65;
    float* reda = redm + 512;

    int tid = threadIdx.x;
    for (int idx = tid; idx < KCODES * DDIM; idx += 512) {
        int row = idx >> 6, col = idx & 63;
        ws[row * 65 + col] = w[idx];           // coalesced
    }
    g_counts[tid] = 0;
    if (tid == 0) { g_loss = 0.0; g_done = 0; }
    __syncthreads();

    int k = tid;
    const float* wr = ws + k * 65;
    float s = 0.0f, amax = 0.0f, asum = 0.0f;
    #pragma unroll 8
    for (int i = 0; i < DDIM; ++i) {
        float v = wr[i];
        s = __fadd_rn(s, __fmul_rn(v, v));
        amax = fmaxf(amax, fabsf(v));
        asum += fabsf(v);
    }
    g_w2[k] = s;
    redm[tid] = amax;
    reda[tid] = asum;
    __syncthreads();
    for (int st = 256; st; st >>= 1) {
        if (tid < st) {
            redm[tid] = fmaxf(redm[tid], redm[tid + st]);
            reda[tid] = fmaxf(reda[tid], reda[tid + st]);
        }
        __syncthreads();
    }
    float wmax = redm[0];
    if (tid == 0) { g_wmax = wmax; g_wabs = reda[0]; }

    float sw = 120.0f / fmaxf(wmax, 1e-20f);
    #pragma unroll
    for (int i4 = 0; i4 < 16; ++i4) {
        int q0 = __float2int_rn(wr[4 * i4 + 0] * sw);
        int q1 = __float2int_rn(wr[4 * i4 + 1] * sw);
        int q2 = __float2int_rn(wr[4 * i4 + 2] * sw);
        int q3 = __float2int_rn(wr[4 * i4 + 3] * sw);
        g_wq[i4 * KCODES + k] = (uint32_t)(q0 & 255) | ((uint32_t)(q1 & 255) << 8)
                              | ((uint32_t)(q2 & 255) << 16) | ((uint32_t)(q3 & 255) << 24);
    }
}

// Main: R13-identical arithmetic; f scoped out of the scan, candidates in
// local memory, 4 CTAs/SM for latency hiding. Last block does the finals.
__global__ __launch_bounds__(NT, 4)
void main_kernel(const float* __restrict__ x, const float* __restrict__ w,
                 float* __restrict__ out) {
    extern __shared__ char sm[];
    uint32_t* Wq  = (uint32_t*)(sm + OFF_WQ);
    float*    w2s = (float*)(sm + OFF_W2);
    int*      hist= (int*)(sm + OFF_H);

    int tid  = threadIdx.x;
    int lane = tid & 31;
    int wid  = tid >> 5;

    int row0 = blockIdx.x * ROWS_PB;
    int b    = row0 >> 12;
    int hw0  = row0 & 4095;
    const size_t xbase = (size_t)b * 262144 + hw0;

    // ---- phase 1: load row, S (sequential NON-fused, matches reference),
    //      stats + int8 pack; f dies before the scan ----
    float S = 0.0f, rmax = 0.0f, fabs_sum = 0.0f;
    uint32_t fq[16];
    {
        float f[DDIM];
        #pragma unroll
        for (int c = 0; c < DDIM; ++c) f[c] = x[xbase + (size_t)c * 4096 + tid];
        #pragma unroll
        for (int c = 0; c < DDIM; ++c) S = __fadd_rn(S, __fmul_rn(f[c], f[c]));
        #pragma unroll
        for (int c = 0; c < DDIM; ++c) { rmax = fmaxf(rmax, fabsf(f[c])); fabs_sum += fabsf(f[c]); }
        float sfl = 120.0f / fmaxf(rmax, 1e-20f);
        #pragma unroll
        for (int i4 = 0; i4 < 16; ++i4) {
            int q0 = __float2int_rn(f[4 * i4 + 0] * sfl);
            int q1 = __float2int_rn(f[4 * i4 + 1] * sfl);
            int q2 = __float2int_rn(f[4 * i4 + 2] * sfl);
            int q3 = __float2int_rn(f[4 * i4 + 3] * sfl);
            fq[i4] = (uint32_t)(q0 & 255) | ((uint32_t)(q1 & 255) << 8)
                   | ((uint32_t)(q2 & 255) << 16) | ((uint32_t)(q3 & 255) << 24);
        }
    }
    float sf = 120.0f / fmaxf(rmax, 1e-20f);

    // ---- stage packed codebook + w2 into smem ----
    for (int idx = tid; idx < 16 * KCODES; idx += NT) {
        int i4 = idx >> 9, k = idx & 511;
        Wq[i4 * WQ_STR + k] = g_wq[idx];
    }
    for (int i = tid; i < KCODES; i += NT) { w2s[i] = g_w2[i]; hist[i] = 0; }
    __syncthreads();

    // ---- sound margin (input-quantization error only; int accum is exact) ----
    float sw  = 120.0f / fmaxf(g_wmax, 1e-20f);
    float dw  = 0.5f / sw;
    float df  = 0.5f / sf;
    float errdot = dw * fabs_sum + df * g_wabs + 64.0f * df * dw;
    float margin = 2.0f * errdot * 1.05f + 1e-5f;
    float inv = 1.0f / (sf * sw);

    float runmin = __int_as_float(0x7f800000);
    int   cnt = 0;
    int   mylist[CAP];          // thread-local (local memory; rarely touched)
    float myvals[CAP];

    // ---- scan: 8 codes per group, 16 packed i-steps, broadcast LDS ----
    for (int g = 0; g < KCODES; g += 8) {
        int acc[8];
        #pragma unroll
        for (int j = 0; j < 8; ++j) acc[j] = 0;
        #pragma unroll
        for (int i4 = 0; i4 < 16; ++i4) {
            const uint32_t* wp = Wq + i4 * WQ_STR + g;
            uint4 wa = *(const uint4*)wp;
            uint4 wb = *(const uint4*)(wp + 4);
            acc[0] = __dp4a((int)fq[i4], (int)wa.x, acc[0]);
            acc[1] = __dp4a((int)fq[i4], (int)wa.y, acc[1]);
            acc[2] = __dp4a((int)fq[i4], (int)wa.z, acc[2]);
            acc[3] = __dp4a((int)fq[i4], (int)wa.w, acc[3]);
            acc[4] = __dp4a((int)fq[i4], (int)wb.x, acc[4]);
            acc[5] = __dp4a((int)fq[i4], (int)wb.y, acc[5]);
            acc[6] = __dp4a((int)fq[i4], (int)wb.z, acc[6]);
            acc[7] = __dp4a((int)fq[i4], (int)wb.w, acc[7]);
        }
        #pragma unroll
        for (int j = 0; j < 8; ++j) {
            float dot = (float)acc[j] * inv;
            float s   = fmaf(-2.0f, dot, w2s[g + j]);
            if (s <= runmin + margin) {
                if (cnt < CAP) { mylist[cnt] = g + j; myvals[cnt] = s; }
                cnt++;
            }
            runmin = fminf(runmin, s);
        }
    }

    // ---- streamed enc zero-fill (hidden under compute) ----
    {
        float* enc = out + ENC_OFF;
        int wrow0 = row0 + wid * 32;
        float4 z = make_float4(0.f, 0.f, 0.f, 0.f);
        for (int rr = 0; rr < 32; ++rr) {
            float* eb = enc + (size_t)(wrow0 + rr) * KCODES;
            float4* v4 = (float4*)(eb + 3);          // 16B aligned
            #pragma unroll
            for (int it = 0; it < 4; ++it) {
                int j = lane + 32 * it;
                if (j < 127) __stcs(&v4[j], z);
            }
            if (lane < 3) __stcs(&eb[lane], 0.f);
            if (lane == 3) __stcs(&eb[511], 0.f);
        }
    }

    // ---- reload f (identical bits) for refinement + outputs ----
    float f[DDIM];
    #pragma unroll
    for (int c = 0; c < DDIM; ++c) f[c] = x[xbase + (size_t)c * 4096 + tid];

    // ---- post-filter vs FINAL min, then exact refinement
    //      (reference-identical rounding, first-index ties) ----
    float thr = runmin + margin;
    float db = __int_as_float(0x7f800000);
    int   kb = 0;
    if (cnt <= CAP) {
        for (int j = 0; j < cnt; ++j) {
            if (myvals[j] > thr) continue;           // drop prefix-min noise
            int k = mylist[j];                       // ascending k order
            const float4* wr = (const float4*)(w + (size_t)k * DDIM);
            float a = 0.0f;
            #pragma unroll
            for (int q = 0; q < 16; ++q) {           // i-order 0..63 sequential
                float4 t = __ldg(&wr[q]);
                a = fmaf(f[4 * q + 0], t.x, a);
                a = fmaf(f[4 * q + 1], t.y, a);
                a = fmaf(f[4 * q + 2], t.z, a);
                a = fmaf(f[4 * q + 3], t.w, a);
            }
            float dd = fmaf(-2.0f, a, __fadd_rn(S, w2s[k]));
            if (dd < db) { db = dd; kb = k; }
        }
    } else {                                         // overflow: full exact scan
        for (int k = 0; k < KCODES; ++k) {
            const float4* wr = (const float4*)(w + (size_t)k * DDIM);
            float a = 0.0f;
            #pragma unroll
            for (int q = 0; q < 16; ++q) {
                float4 t = __ldg(&wr[q]);
                a = fmaf(f[4 * q + 0], t.x, a);
                a = fmaf(f[4 * q + 1], t.y, a);
                a = fmaf(f[4 * q + 2], t.z, a);
                a = fmaf(f[4 * q + 3], t.w, a);
            }
            float dd = fmaf(-2.0f, a, __fadd_rn(S, w2s[k]));
            if (dd < db) { db = dd; kb = k; }
        }
    }

    g_idx[row0 + tid] = kb;
    atomicAdd(&hist[kb], 1);

    __syncthreads();   // orders the 1-write after this block's zero-fill

    // ---- one-hot 1-write (fused) ----
    out[ENC_OFF + (size_t)(row0 + tid) * KCODES + kb] = 1.0f;

    // ---- quantized output + loss partials (reference rounding) ----
    const float* wbr = w + (size_t)kb * DDIM;
    float* outp = out + xbase;
    float lsum = 0.0f;
    #pragma unroll
    for (int c = 0; c < DDIM; ++c) {
        float q  = wbr[c];
        float dd = __fsub_rn(q, f[c]);
        outp[(size_t)c * 4096 + tid] = __fadd_rn(f[c], dd);
        lsum = fmaf(dd, dd, lsum);
    }
    #pragma unroll
    for (int o = 16; o; o >>= 1) lsum += __shfl_down_sync(0xffffffffu, lsum, o);
    if (lane == 0) atomicAdd(&g_loss, (double)lsum);

    for (int i = tid; i < KCODES; i += NT)
        if (hist[i]) atomicAdd(&g_counts[i], hist[i]);

    // ---- completion ticket; last block computes loss + perplexity ----
    __syncthreads();
    __shared__ unsigned s_ticket;
    if (tid == 0) {
        __threadfence();
        s_ticket = atomicAdd(&g_done, 1u);
    }
    __syncthreads();
    if (s_ticket == NBLK - 1) {
        __threadfence();                             // acquire side
        double* red = (double*)(sm + OFF_WQ);        // 512 doubles (region free)
        for (int i = tid; i < KCODES; i += NT) {
            int c = atomicAdd(&g_counts[i], 0);      // coherent read
            float p = (float)c * (1.0f / 131072.0f);
            float term = __fmul_rn(p, logf(__fadd_rn(p, 1e-10f)));
            red[i] = (double)term;
        }
        __syncthreads();
        for (int s = 256; s; s >>= 1) {              // same pairing tree as before
            for (int t = tid; t < s; t += NT) red[t] += red[t + s];
            __syncthreads();
        }
        if (tid == 0) {
            out[PERP_OFF] = expf(-(float)red[0]);
            double gl = atomicAdd(&g_loss, 0.0);     // coherent read
            float m = (float)(gl / (double)QSIZE);
            out[QSIZE] = __fadd_rn(m, __fmul_rn(0.25f, m));
            g_done = 0;                              // reset for graph replay
        }
    }
}

extern "C" void kernel_launch(void* const* d_in, const int* in_sizes, int n_in,
                              void* d_out, int out_size) {
    const float* x = (const float*)d_in[0];
    const float* w = (const float*)d_in[1];
    float* out = (float*)d_out;

    cudaFuncSetAttribute(prep_kernel, cudaFuncAttributeMaxDynamicSharedMemorySize,
                         512 * 65 * 4 + 1024 * 4);
    cudaFuncSetAttribute(main_kernel, cudaFuncAttributeMaxDynamicSharedMemorySize,
                         SMEM_BYTES);

    prep_kernel<<<1, 512, 512 * 65 * 4 + 1024 * 4>>>(w);
    main_kernel<<<NBLK, NT, SMEM_BYTES>>>(x, w, out);
}